// round 10
// baseline (speedup 1.0000x reference)
#include <cuda_runtime.h>
#include <math.h>

#define NE_ 100000
#define NR_ 256
#define H_ 128
#define E_ 250000
#define NROWS_ (NE_ + NR_)

__device__ float g_h[(size_t)NROWS_ * H_];
__device__ float g_k[6][(size_t)NROWS_ * H_];
__device__ float g_q[(size_t)NE_ * H_];
__device__ float g_den[(size_t)NE_ * 8];

// k-pair interleaved weights: W2[(k/2)*NCOLS + c] = (W[k][c], W[k+1][c]) as b64
__device__ unsigned long long g_w2_spW1[64 * 256];
__device__ unsigned long long g_w2_spW2[128 * 128];
__device__ unsigned long long g_w2_tmW1[64 * 64];
__device__ unsigned long long g_w2_tmW2[32 * 128];
__device__ unsigned long long g_w2_Wq[64 * 128];
__device__ unsigned long long g_w2_Wk[64 * 128];
__device__ unsigned long long g_w2_Wv[64 * 128];
__device__ unsigned long long g_w2_wgW1[128 * 128];

__device__ __forceinline__ unsigned long long pk2(float x, float y) {
    unsigned long long r; asm("mov.b64 %0,{%1,%2};" : "=l"(r) : "f"(x), "f"(y)); return r;
}
__device__ __forceinline__ void upk2(unsigned long long v, float& x, float& y) {
    asm("mov.b64 {%0,%1},%2;" : "=f"(x), "=f"(y) : "l"(v));
}
__device__ __forceinline__ void ffma2(unsigned long long& c, unsigned long long a, unsigned long long b) {
    asm("fma.rn.f32x2 %0,%1,%2,%0;" : "+l"(c) : "l"(a), "l"(b));
}
__device__ __forceinline__ float sigmoid_f(float x) { return 1.f / (1.f + expf(-x)); }
__device__ __forceinline__ float gelu_f(float x) { return 0.5f * x * (1.f + erff(x * 0.70710678118654752f)); }
__device__ __forceinline__ float softplus_f(float x) {
    return x > 0.f ? x + log1pf(expf(-x)) : log1pf(expf(x));
}

// C[TILE,NCOLS] = As[TILE,KDIM](stride lda) @ W (k-pair interleaved W2), epilogue applied.
// NT threads: WCOL=NCOLS/32 warp column-stripes x WROW row groups. Lane owns ONE
// column. Two k per FFMA2 (even/odd split accumulator): A pairs come straight
// from LDS.128 (no MOVs), W pairs straight from LDG.64 (pre-interleaved).
template<int TILE, int NCOLS, int KDIM, int NT, typename Epi>
__device__ __forceinline__ void gemmP(const float* As, int lda,
                                      const unsigned long long* __restrict__ W2,
                                      float* Cs, int ldc, Epi epi)
{
    constexpr int NW   = NT / 32;
    constexpr int WCOL = NCOLS / 32;
    constexpr int WROW = NW / WCOL;
    constexpr int ROWS = TILE / WROW;
    static_assert(WROW * WCOL == NW && ROWS * WROW == TILE, "bad partition");
    const int lane = threadIdx.x & 31;
    const int w    = threadIdx.x >> 5;
    const int wc   = w % WCOL;
    const int wr   = w / WCOL;
    const int c    = wc * 32 + lane;
    unsigned long long acc[ROWS];
#pragma unroll
    for (int i = 0; i < ROWS; i++) acc[i] = 0ull;
    const float* a0 = As + (size_t)(wr * ROWS) * lda;
    const unsigned long long* Wp = W2 + c;
#pragma unroll 2
    for (int k0 = 0; k0 < KDIM; k0 += 4) {
        unsigned long long wv0 = Wp[(size_t)(k0 >> 1) * NCOLS];
        unsigned long long wv1 = Wp[(size_t)((k0 >> 1) + 1) * NCOLS];
#pragma unroll
        for (int i = 0; i < ROWS; i++) {
            ulonglong2 av = *reinterpret_cast<const ulonglong2*>(a0 + (size_t)i * lda + k0);
            ffma2(acc[i], av.x, wv0);
            ffma2(acc[i], av.y, wv1);
        }
    }
#pragma unroll
    for (int i = 0; i < ROWS; i++) {
        int row = wr * ROWS + i;
        float x, y; upk2(acc[i], x, y);
        float v = x + y;
        epi(row, c, v);
        Cs[(size_t)row * ldc + c] = v;
    }
}

__global__ void STG_repack_kernel(
    const float* __restrict__ spW1, const float* __restrict__ spW2,
    const float* __restrict__ tmW1, const float* __restrict__ tmW2,
    const float* __restrict__ Wq, const float* __restrict__ Wk,
    const float* __restrict__ Wv, const float* __restrict__ wgW1)
{
    int i = blockIdx.x * 256 + threadIdx.x;
    if (i < 16384) { int kp = i >> 8, c = i & 255;
        g_w2_spW1[i] = pk2(spW1[(2*kp)*256 + c], spW1[(2*kp+1)*256 + c]); return; }
    i -= 16384;
    if (i < 16384) { int kp = i >> 7, c = i & 127;
        g_w2_spW2[i] = pk2(spW2[(2*kp)*128 + c], spW2[(2*kp+1)*128 + c]); return; }
    i -= 16384;
    if (i < 4096) { int kp = i >> 6, c = i & 63;
        g_w2_tmW1[i] = pk2(tmW1[(2*kp)*64 + c], tmW1[(2*kp+1)*64 + c]); return; }
    i -= 4096;
    if (i < 4096) { int kp = i >> 7, c = i & 127;
        g_w2_tmW2[i] = pk2(tmW2[(2*kp)*128 + c], tmW2[(2*kp+1)*128 + c]); return; }
    i -= 4096;
    if (i < 8192) { int kp = i >> 7, c = i & 127;
        g_w2_Wq[i] = pk2(Wq[(2*kp)*128 + c], Wq[(2*kp+1)*128 + c]); return; }
    i -= 8192;
    if (i < 8192) { int kp = i >> 7, c = i & 127;
        g_w2_Wk[i] = pk2(Wk[(2*kp)*128 + c], Wk[(2*kp+1)*128 + c]); return; }
    i -= 8192;
    if (i < 8192) { int kp = i >> 7, c = i & 127;
        g_w2_Wv[i] = pk2(Wv[(2*kp)*128 + c], Wv[(2*kp+1)*128 + c]); return; }
    i -= 8192;
    if (i < 16384) { int kp = i >> 7, c = i & 127;
        g_w2_wgW1[i] = pk2(wgW1[(2*kp)*128 + c], wgW1[(2*kp+1)*128 + c]); return; }
}

__global__ void STG_zero_kernel() {
    size_t i = ((size_t)blockIdx.x * 256 + threadIdx.x) * 4;
    const size_t nH = (size_t)NE_ * H_;
    if (i < nH) {
        *reinterpret_cast<float4*>(g_h + i) = make_float4(0.f, 0.f, 0.f, 0.f);
    } else {
        size_t j = i - nH;
        if (j < (size_t)NE_ * 8)
            *reinterpret_cast<float4*>(g_den + j) = make_float4(0.f, 0.f, 0.f, 0.f);
    }
}

__global__ __launch_bounds__(256) void STG_qall_kernel(
    const float* __restrict__ ent, const float* __restrict__ bq)
{
    extern __shared__ float sm[];
    float* h_s = sm;                 // 32*128
    float* o_s = sm + 32 * 128;      // 32*128
    const int row0 = blockIdx.x * 32;
    for (int t = threadIdx.x; t < 32 * 32; t += 256) {
        int r = t >> 5, c = (t & 31) * 4; int g = row0 + r;
        float4 v = make_float4(0.f, 0.f, 0.f, 0.f);
        if (g < NE_) v = *reinterpret_cast<const float4*>(ent + (size_t)g * H_ + c);
        *reinterpret_cast<float4*>(h_s + r * H_ + c) = v;
    }
    __syncthreads();
    gemmP<32, 128, 128, 256>(h_s, 128, g_w2_Wq, o_s, 128,
        [&](int r, int c, float& v) { v += bq[c]; });
    __syncthreads();
    for (int t = threadIdx.x; t < 32 * 32; t += 256) {
        int r = t >> 5, c = (t & 31) * 4; int g = row0 + r;
        if (g < NE_)
            *reinterpret_cast<float4*>(g_q + (size_t)g * H_ + c) =
                *reinterpret_cast<const float4*>(o_s + r * H_ + c);
    }
}

__global__ __launch_bounds__(256, 2) void STG_edge_kernel(
    const float* __restrict__ ent, const float* __restrict__ drel,
    const float* __restrict__ bk, const float* __restrict__ bv,
    const float* __restrict__ wgW1, const float* __restrict__ wgb1,
    const float* __restrict__ wgW2, const float* __restrict__ wgb2,
    const float* __restrict__ time_coeff,
    const float* __restrict__ edge_time, const float* __restrict__ query_time,
    const int* __restrict__ src, const int* __restrict__ dst, const int* __restrict__ etyp)
{
    extern __shared__ float sm[];
    float* wi_s  = sm;                   // 32*256 : [src_e | rel_e*tm]
    float* hid_s = wi_s + 32 * 256;      // 32*128
    float* k_s   = hid_s + 32 * 128;     // 32*128
    float* v_s   = k_s + 32 * 128;       // 32*128
    float* tm_s  = v_s + 32 * 128;       // 32
    float* dw_s  = tm_s + 32;            // 32
    float* ex_s  = dw_s + 32;            // 32*8
    int*   dst_s = (int*)(ex_s + 32 * 8);
    int*   src_s = dst_s + 32;
    int*   et_s  = src_s + 32;
    int*   vld_s = et_s + 32;

    const int tid = threadIdx.x;
    if (tid < 32) {
        int e = blockIdx.x * 32 + tid;
        int vld = (e < E_);
        int ee = vld ? e : 0;
        int s = src[ee], d = dst[ee], t = etyp[ee];
        float tc = fabsf(time_coeff[0]) + 1e-9f;
        float dte = (query_time[d] - edge_time[ee]) / tc;
        tm_s[tid] = sigmoid_f(dte);
        dst_s[tid] = d; src_s[tid] = s; et_s[tid] = t; vld_s[tid] = vld;
    }
    __syncthreads();

    for (int t = tid; t < 32 * 64; t += 256) {
        int r = t >> 6; int c = (t & 63) * 4;
        float4 v;
        if (c < 128) {
            v = *reinterpret_cast<const float4*>(ent + (size_t)src_s[r] * H_ + c);
        } else {
            float4 rv = *reinterpret_cast<const float4*>(drel + (size_t)et_s[r] * H_ + (c - 128));
            float tmv = tm_s[r];
            v.x = rv.x * tmv; v.y = rv.y * tmv; v.z = rv.z * tmv; v.w = rv.w * tmv;
        }
        *reinterpret_cast<float4*>(wi_s + r * 256 + c) = v;
    }
    __syncthreads();

    // hidden = relu(wi @ wgW1[0:256] + tm*wgW1[256] + b1)   (wgW1 is [257,128])
    gemmP<32, 128, 256, 256>(wi_s, 256, g_w2_wgW1, hid_s, 128,
        [&](int r, int c, float& v) {
            v = fmaxf(v + wgb1[c] + tm_s[r] * wgW1[256 * 128 + c], 0.f);
        });
    __syncthreads();

    {   // dw = sigmoid(hidden . wgW2 + b2), 8 threads/edge
        int r = tid >> 3, part = tid & 7;
        float s = 0.f;
#pragma unroll
        for (int j = 0; j < 16; j++) { int d = part * 16 + j; s += hid_s[r * 128 + d] * wgW2[d]; }
        s += __shfl_xor_sync(0xffffffffu, s, 1);
        s += __shfl_xor_sync(0xffffffffu, s, 2);
        s += __shfl_xor_sync(0xffffffffu, s, 4);
        if (part == 0) dw_s[r] = sigmoid_f(s + wgb2[0]);
    }
    __syncthreads();

    // msg = src_e * rel_e * dw  (in place over src half)
    for (int t = tid; t < 32 * 32; t += 256) {
        int r = t >> 5, c = (t & 31) * 4;
        float4 a = *reinterpret_cast<const float4*>(wi_s + r * 256 + c);
        float4 b = *reinterpret_cast<const float4*>(wi_s + r * 256 + 128 + c);
        float dw = dw_s[r];
        a.x *= b.x * dw; a.y *= b.y * dw; a.z *= b.z * dw; a.w *= b.w * dw;
        *reinterpret_cast<float4*>(wi_s + r * 256 + c) = a;
    }
    __syncthreads();

    gemmP<32, 128, 128, 256>(wi_s, 256, g_w2_Wk, k_s, 128,
        [&](int r, int c, float& v) { v += bk[c]; });
    gemmP<32, 128, 128, 256>(wi_s, 256, g_w2_Wv, v_s, 128,
        [&](int r, int c, float& v) { v += bv[c]; });
    __syncthreads();

    {   // scores -> exp -> denominator (softmax shift skipped: exact invariance, |s| tiny here)
        int r = tid >> 3, hh = tid & 7;
        int d = dst_s[r]; int vld = vld_s[r];
        const float* qrow = g_q + (size_t)d * H_;
        float s = 0.f;
#pragma unroll
        for (int j = 0; j < 16; j += 4) {
            float4 qv = *reinterpret_cast<const float4*>(qrow + hh * 16 + j);
            float4 kv = *reinterpret_cast<const float4*>(k_s + r * 128 + hh * 16 + j);
            s += qv.x * kv.x + qv.y * kv.y + qv.z * kv.z + qv.w * kv.w;
        }
        float ex = expf(s * 0.25f);
        ex_s[r * 8 + hh] = ex;
        if (vld) atomicAdd(&g_den[(size_t)d * 8 + hh], ex);
    }
    __syncthreads();

    {   // numerator scatter: 8 threads/edge, 16 cols each
        int r = tid >> 3, part = tid & 7;
        if (vld_s[r]) {
            int d = dst_s[r];
            float* xr = g_h + (size_t)d * H_;
            float exh0 = ex_s[r * 8 + part];
#pragma unroll
            for (int j = 0; j < 16; j++) {
                int c = part * 16 + j;
                atomicAdd(&xr[c], exh0 * v_s[r * 128 + c]);
            }
        }
    }
}

__global__ void STG_norm_kernel() {
    size_t i = (size_t)blockIdx.x * 256 + threadIdx.x;
    if (i >= (size_t)NE_ * H_) return;
    size_t n = i >> 7; int c = (int)(i & 127);
    float den = g_den[n * 8 + (c >> 4)];
    float x = g_h[i];
    g_h[i] = den > 0.f ? x / den : 0.f;
}

__global__ void STG_relcopy_kernel(const float* __restrict__ rel) {
    int i = blockIdx.x * 256 + threadIdx.x;
    if (i < NR_ * H_) g_h[(size_t)NE_ * H_ + i] = rel[i];
}

__global__ __launch_bounds__(512, 2) void STG_feval_kernel(
    int nk, float c1, float c2, float c3, float c4, float c5, int kout_idx,
    const float* __restrict__ spb1, const float* __restrict__ spb2,
    const float* __restrict__ tmb1, const float* __restrict__ tmb2,
    const float* __restrict__ fgW,  const float* __restrict__ fgb)
{
    extern __shared__ float sm[];
    float* h_s   = sm;               // 32*128 (reused as sp)
    float* a1_s  = sm + 32 * 128;    // 32*256 (reused as tm)
    float* a2_s  = a1_s + 32 * 256;  // 32*64
    float* sp_s  = h_s;
    float* tm2_s = a1_s;

    const int row0 = blockIdx.x * 32;
    for (int t = threadIdx.x; t < 32 * 32; t += 512) {
        int r = t >> 5, c = (t & 31) * 4; int g = row0 + r;
        float4 v = make_float4(0.f, 0.f, 0.f, 0.f);
        if (g < NROWS_) {
            size_t idx = (size_t)g * H_ + c;
            v = *reinterpret_cast<const float4*>(g_h + idx);
            float4 a;
            if (nk > 0) { a = *reinterpret_cast<const float4*>(g_k[0] + idx);
                v.x += c1 * a.x; v.y += c1 * a.y; v.z += c1 * a.z; v.w += c1 * a.w; }
            if (nk > 1) { a = *reinterpret_cast<const float4*>(g_k[1] + idx);
                v.x += c2 * a.x; v.y += c2 * a.y; v.z += c2 * a.z; v.w += c2 * a.w; }
            if (nk > 2) { a = *reinterpret_cast<const float4*>(g_k[2] + idx);
                v.x += c3 * a.x; v.y += c3 * a.y; v.z += c3 * a.z; v.w += c3 * a.w; }
            if (nk > 3) { a = *reinterpret_cast<const float4*>(g_k[3] + idx);
                v.x += c4 * a.x; v.y += c4 * a.y; v.z += c4 * a.z; v.w += c4 * a.w; }
            if (nk > 4) { a = *reinterpret_cast<const float4*>(g_k[4] + idx);
                v.x += c5 * a.x; v.y += c5 * a.y; v.z += c5 * a.z; v.w += c5 * a.w; }
        }
        *reinterpret_cast<float4*>(h_s + r * H_ + c) = v;
    }
    __syncthreads();

    gemmP<32, 256, 128, 512>(h_s, 128, g_w2_spW1, a1_s, 256,
        [&](int r, int c, float& v) { v = gelu_f(v + spb1[c]); });
    gemmP<32, 64, 128, 512>(h_s, 128, g_w2_tmW1, a2_s, 64,
        [&](int r, int c, float& v) { v = softplus_f(v + tmb1[c]); });
    __syncthreads();

    gemmP<32, 128, 256, 512>(a1_s, 256, g_w2_spW2, sp_s, 128,
        [&](int r, int c, float& v) { v += spb2[c]; });
    __syncthreads();

    gemmP<32, 128, 64, 512>(a2_s, 64, g_w2_tmW2, tm2_s, 128,
        [&](int r, int c, float& v) { v += tmb2[c]; });
    __syncthreads();

    {   // gate + output: 16 threads/row, 8 cols each
        int r = threadIdx.x >> 4, part = threadIdx.x & 15;
        float s0 = 0.f, s1 = 0.f;
#pragma unroll
        for (int jj = 0; jj < 8; jj++) {
            int d = part * 8 + jj;
            float spv = sp_s[r * 128 + d], tmv = tm2_s[r * 128 + d];
            s0 += spv * fgW[2 * d]     + tmv * fgW[2 * (128 + d)];
            s1 += spv * fgW[2 * d + 1] + tmv * fgW[2 * (128 + d) + 1];
        }
        s0 += __shfl_xor_sync(0xffffffffu, s0, 1);
        s1 += __shfl_xor_sync(0xffffffffu, s1, 1);
        s0 += __shfl_xor_sync(0xffffffffu, s0, 2);
        s1 += __shfl_xor_sync(0xffffffffu, s1, 2);
        s0 += __shfl_xor_sync(0xffffffffu, s0, 4);
        s1 += __shfl_xor_sync(0xffffffffu, s1, 4);
        s0 += __shfl_xor_sync(0xffffffffu, s0, 8);
        s1 += __shfl_xor_sync(0xffffffffu, s1, 8);
        float g0 = sigmoid_f(s0 + fgb[0]);
        float g1 = sigmoid_f(s1 + fgb[1]);
        int g = row0 + r;
        if (g < NROWS_) {
            float* ko = g_k[kout_idx] + (size_t)g * H_;
#pragma unroll
            for (int jj = 0; jj < 8; jj += 4) {
                int d = part * 8 + jj;
                float4 o;
                o.x = g0 * sp_s[r * 128 + d + 0] + g1 * tm2_s[r * 128 + d + 0];
                o.y = g0 * sp_s[r * 128 + d + 1] + g1 * tm2_s[r * 128 + d + 1];
                o.z = g0 * sp_s[r * 128 + d + 2] + g1 * tm2_s[r * 128 + d + 2];
                o.w = g0 * sp_s[r * 128 + d + 3] + g1 * tm2_s[r * 128 + d + 3];
                *reinterpret_cast<float4*>(ko + d) = o;
            }
        }
    }
}

__global__ void STG_combine_kernel(float b1, float b3, float b4, float b5, float b6) {
    size_t i = ((size_t)blockIdx.x * 256 + threadIdx.x) * 4;
    if (i >= (size_t)NROWS_ * H_) return;
    float4 h = *reinterpret_cast<const float4*>(g_h + i);
    float4 a = *reinterpret_cast<const float4*>(g_k[0] + i);
    float4 c = *reinterpret_cast<const float4*>(g_k[2] + i);
    float4 d = *reinterpret_cast<const float4*>(g_k[3] + i);
    float4 e = *reinterpret_cast<const float4*>(g_k[4] + i);
    float4 f = *reinterpret_cast<const float4*>(g_k[5] + i);
    h.x += b1 * a.x + b3 * c.x + b4 * d.x + b5 * e.x + b6 * f.x;
    h.y += b1 * a.y + b3 * c.y + b4 * d.y + b5 * e.y + b6 * f.y;
    h.z += b1 * a.z + b3 * c.z + b4 * d.z + b5 * e.z + b6 * f.z;
    h.w += b1 * a.w + b3 * c.w + b4 * d.w + b5 * e.w + b6 * f.w;
    *reinterpret_cast<float4*>(g_h + i) = h;
}

__global__ void STG_outcopy_kernel(float* __restrict__ out, int n4) {
    int i = blockIdx.x * 256 + threadIdx.x;
    if (i < n4)
        *reinterpret_cast<float4*>(out + (size_t)i * 4) =
            *reinterpret_cast<const float4*>(g_h + (size_t)i * 4);
}

extern "C" void kernel_launch(void* const* d_in, const int* in_sizes, int n_in,
                              void* d_out, int out_size)
{
    (void)in_sizes; (void)n_in;
    const float* ent  = (const float*)d_in[0];
    const float* rel  = (const float*)d_in[1];
    const float* drel = (const float*)d_in[2];
    const float* Wq   = (const float*)d_in[3];
    const float* bq   = (const float*)d_in[4];
    const float* Wk   = (const float*)d_in[5];
    const float* bk   = (const float*)d_in[6];
    const float* Wv   = (const float*)d_in[7];
    const float* bv   = (const float*)d_in[8];
    const float* tcoef= (const float*)d_in[9];
    const float* wgW1 = (const float*)d_in[10];
    const float* wgb1 = (const float*)d_in[11];
    const float* wgW2 = (const float*)d_in[12];
    const float* wgb2 = (const float*)d_in[13];
    const float* spW1 = (const float*)d_in[14];
    const float* spb1 = (const float*)d_in[15];
    const float* spW2 = (const float*)d_in[16];
    const float* spb2 = (const float*)d_in[17];
    const float* tmW1 = (const float*)d_in[18];
    const float* tmb1 = (const float*)d_in[19];
    const float* tmW2 = (const float*)d_in[20];
    const float* tmb2 = (const float*)d_in[21];
    const float* fgW  = (const float*)d_in[22];
    const float* fgb  = (const float*)d_in[23];
    const float* edge_time  = (const float*)d_in[24];
    const float* query_time = (const float*)d_in[25];
    const int* src  = (const int*)d_in[26];
    const int* dst  = (const int*)d_in[27];
    const int* etyp = (const int*)d_in[28];
    float* out = (float*)d_out;

    const int SM_QALL = 2 * 32 * 128 * 4;                                   // 32768
    const int SM_EDGE = (32*256 + 3*32*128 + 32 + 32 + 32*8 + 4*32) * 4;    // 83712
    const int SM_FEVL = (32*128 + 32*256 + 32*64) * 4;                      // 57344
    cudaFuncSetAttribute(STG_qall_kernel,  cudaFuncAttributeMaxDynamicSharedMemorySize, SM_QALL);
    cudaFuncSetAttribute(STG_edge_kernel,  cudaFuncAttributeMaxDynamicSharedMemorySize, SM_EDGE);
    cudaFuncSetAttribute(STG_feval_kernel, cudaFuncAttributeMaxDynamicSharedMemorySize, SM_FEVL);

    STG_repack_kernel<<<(81920 + 255) / 256, 256>>>(spW1, spW2, tmW1, tmW2, Wq, Wk, Wv, wgW1);

    {
        size_t tot4 = ((size_t)NE_ * H_ + (size_t)NE_ * 8) / 4;
        int nb = (int)((tot4 + 255) / 256);
        STG_zero_kernel<<<nb, 256>>>();
    }
    STG_qall_kernel<<<(NE_ + 31) / 32, 256, SM_QALL>>>(ent, bq);
    STG_edge_kernel<<<(E_ + 31) / 32, 256, SM_EDGE>>>(
        ent, drel, bk, bv, wgW1, wgb1, wgW2, wgb2,
        tcoef, edge_time, query_time, src, dst, etyp);
    {
        size_t tot = (size_t)NE_ * H_;
        STG_norm_kernel<<<(int)((tot + 255) / 256), 256>>>();
    }
    STG_relcopy_kernel<<<(NR_ * H_ + 255) / 256, 256>>>(rel);

    const float dt = 1.0f / 8.0f;
    const int FB = (NROWS_ + 31) / 32;
    const int CB = (int)(((size_t)NROWS_ * H_ / 4 + 255) / 256);

    for (int s = 0; s < 8; s++) {
        STG_feval_kernel<<<FB, 512, SM_FEVL>>>(0, 0.f, 0.f, 0.f, 0.f, 0.f, 0,
            spb1, spb2, tmb1, tmb2, fgW, fgb);
        STG_feval_kernel<<<FB, 512, SM_FEVL>>>(1, dt * 0.2f, 0.f, 0.f, 0.f, 0.f, 1,
            spb1, spb2, tmb1, tmb2, fgW, fgb);
        STG_feval_kernel<<<FB, 512, SM_FEVL>>>(2,
            dt * (3.0f / 40.0f), dt * (9.0f / 40.0f), 0.f, 0.f, 0.f, 2,
            spb1, spb2, tmb1, tmb2, fgW, fgb);
        STG_feval_kernel<<<FB, 512, SM_FEVL>>>(3,
            dt * (44.0f / 45.0f), dt * (-56.0f / 15.0f), dt * (32.0f / 9.0f), 0.f, 0.f, 3,
            spb1, spb2, tmb1, tmb2, fgW, fgb);
        STG_feval_kernel<<<FB, 512, SM_FEVL>>>(4,
            dt * (19372.0f / 6561.0f), dt * (-25360.0f / 2187.0f),
            dt * (64448.0f / 6561.0f), dt * (-212.0f / 729.0f), 0.f, 4,
            spb1, spb2, tmb1, tmb2, fgW, fgb);
        STG_feval_kernel<<<FB, 512, SM_FEVL>>>(5,
            dt * (9017.0f / 3168.0f), dt * (-355.0f / 33.0f),
            dt * (46732.0f / 5247.0f), dt * (49.0f / 176.0f),
            dt * (-5103.0f / 18656.0f), 5,
            spb1, spb2, tmb1, tmb2, fgW, fgb);
        STG_combine_kernel<<<CB, 256>>>(
            dt * (35.0f / 384.0f), dt * (500.0f / 1113.0f), dt * (125.0f / 192.0f),
            dt * (-2187.0f / 6784.0f), dt * (11.0f / 84.0f));
    }

    {
        int n4 = out_size / 4;
        STG_outcopy_kernel<<<(n4 + 255) / 256, 256>>>(out, n4);
    }
}

// round 11
// speedup vs baseline: 1.1261x; 1.1261x over previous
#include <cuda_runtime.h>
#include <math.h>

#define NE_ 100000
#define NR_ 256
#define H_ 128
#define E_ 250000
#define NROWS_ (NE_ + NR_)

__device__ float g_h[(size_t)NROWS_ * H_];
__device__ float g_k[6][(size_t)NROWS_ * H_];
__device__ float g_q[(size_t)NE_ * H_];
__device__ float g_den[(size_t)NE_ * 8];

// tf32 hi/lo fragment-packed weights: uint4 = (b0_hi, b1_hi, b0_lo, b1_lo)
// index = (kt*NT + nt)*32 + lane ; b0 = W[kt*8 + lane%4][nt*8 + lane/4], b1 = +4 k
__device__ uint4 g_f_spW1[16 * 32 * 32];   // K=128, N=256
__device__ uint4 g_f_spW2[32 * 16 * 32];   // K=256, N=128
__device__ uint4 g_f_tmW1[16 * 8 * 32];    // K=128, N=64
__device__ uint4 g_f_tmW2[8 * 16 * 32];    // K=64,  N=128

__device__ __forceinline__ unsigned long long pk2(float x, float y) {
    unsigned long long r; asm("mov.b64 %0,{%1,%2};" : "=l"(r) : "f"(x), "f"(y)); return r;
}
__device__ __forceinline__ void upk2(unsigned long long v, float& x, float& y) {
    asm("mov.b64 {%0,%1},%2;" : "=f"(x), "=f"(y) : "l"(v));
}
__device__ __forceinline__ void ffma2(unsigned long long& c, unsigned long long a, unsigned long long b) {
    asm("fma.rn.f32x2 %0,%1,%2,%0;" : "+l"(c) : "l"(a), "l"(b));
}
__device__ __forceinline__ float sigmoid_f(float x) { return 1.f / (1.f + expf(-x)); }
__device__ __forceinline__ float gelu_f(float x) { return 0.5f * x * (1.f + erff(x * 0.70710678118654752f)); }
__device__ __forceinline__ float softplus_f(float x) {
    return x > 0.f ? x + log1pf(expf(-x)) : log1pf(expf(x));
}

__device__ __forceinline__ void tf32s(float v, unsigned& h, unsigned& l) {
    asm("cvt.rna.tf32.f32 %0,%1;" : "=r"(h) : "f"(v));
    float r = v - __uint_as_float(h);
    asm("cvt.rna.tf32.f32 %0,%1;" : "=r"(l) : "f"(r));
}

__device__ __forceinline__ void mma8(float4& d, unsigned a0, unsigned a1, unsigned a2, unsigned a3,
                                     unsigned b0, unsigned b1) {
    asm volatile(
        "mma.sync.aligned.m16n8k8.row.col.f32.tf32.tf32.f32 "
        "{%0,%1,%2,%3},{%4,%5,%6,%7},{%8,%9},{%0,%1,%2,%3};"
        : "+f"(d.x), "+f"(d.y), "+f"(d.z), "+f"(d.w)
        : "r"(a0), "r"(a1), "r"(a2), "r"(a3), "r"(b0), "r"(b1));
}

// acc[NTILES] += A(16 rows at arow, K=KTILES*8, smem stride SA) @ W-frags (3xTF32).
// All 256 threads participate (Wstage barriers). Warp-uniform control flow.
template<int KTILES, int NTILES, int NT_TOT, int SA>
__device__ void mma_gemm(const float* As, int arow, const uint4* __restrict__ Wg, int ntoff,
                         uint4* Ws, float4* acc, int tid, int lane)
{
    const int g = lane >> 2, q = lane & 3;
    for (int ktc = 0; ktc < KTILES; ktc += 2) {
        __syncthreads();
        for (int t = tid; t < 2 * NTILES * 32; t += 256) {
            int kk = t / (NTILES * 32);
            int nt = (t >> 5) % NTILES;
            int ln = t & 31;
            Ws[t] = Wg[((size_t)(ktc + kk) * NT_TOT + ntoff + nt) * 32 + ln];
        }
        __syncthreads();
#pragma unroll
        for (int kk = 0; kk < 2; kk++) {
            int k0 = (ktc + kk) * 8;
            const float* Ar = As + (size_t)(arow + g) * SA + k0 + q;
            float f0 = Ar[0];
            float f1 = Ar[8 * SA];
            float f2 = Ar[4];
            float f3 = Ar[8 * SA + 4];
            unsigned ah0, al0, ah1, al1, ah2, al2, ah3, al3;
            tf32s(f0, ah0, al0); tf32s(f1, ah1, al1);
            tf32s(f2, ah2, al2); tf32s(f3, ah3, al3);
#pragma unroll
            for (int nt = 0; nt < NTILES; nt++) {
                uint4 b = Ws[(kk * NTILES + nt) * 32 + lane];
                mma8(acc[nt], ah0, ah1, ah2, ah3, b.x, b.y);
                mma8(acc[nt], ah0, ah1, ah2, ah3, b.z, b.w);
                mma8(acc[nt], al0, al1, al2, al3, b.x, b.y);
            }
        }
    }
}

__device__ __forceinline__ uint4 mk_frag(const float* W, int N, int k0, int n0) {
    unsigned xh, xl, yh, yl;
    tf32s(W[(size_t)k0 * N + n0], xh, xl);
    tf32s(W[(size_t)(k0 + 4) * N + n0], yh, yl);
    return make_uint4(xh, yh, xl, yl);
}

__global__ void STG_fragrepack_kernel(
    const float* __restrict__ spW1, const float* __restrict__ spW2,
    const float* __restrict__ tmW1, const float* __restrict__ tmW2)
{
    int i = blockIdx.x * 256 + threadIdx.x;
    if (i < 16384) {
        int kt = i >> 10, nt = (i >> 5) & 31, ln = i & 31;
        g_f_spW1[i] = mk_frag(spW1, 256, kt * 8 + (ln & 3), nt * 8 + (ln >> 2));
        return;
    }
    i -= 16384;
    if (i < 16384) {
        int kt = i >> 9, nt = (i >> 5) & 15, ln = i & 31;
        g_f_spW2[i] = mk_frag(spW2, 128, kt * 8 + (ln & 3), nt * 8 + (ln >> 2));
        return;
    }
    i -= 16384;
    if (i < 4096) {
        int kt = i >> 8, nt = (i >> 5) & 7, ln = i & 31;
        g_f_tmW1[i] = mk_frag(tmW1, 64, kt * 8 + (ln & 3), nt * 8 + (ln >> 2));
        return;
    }
    i -= 4096;
    if (i < 4096) {
        int kt = i >> 9, nt = (i >> 5) & 15, ln = i & 31;
        g_f_tmW2[i] = mk_frag(tmW2, 128, kt * 8 + (ln & 3), nt * 8 + (ln >> 2));
        return;
    }
}

// ---------------- stage-1 (unchanged from the 25.76ms version) ----------------
template<int TILE, int NCOLS, int KDIM, typename Epi>
__device__ __forceinline__ void gemmC(const float* As, int lda,
                                      const float* __restrict__ W,
                                      float* Cs, int ldc, Epi epi)
{
    constexpr int WCOL = (NCOLS / 64) < 8 ? (NCOLS / 64) : 8;
    constexpr int WROW = 8 / WCOL;
    constexpr int ROWS = TILE / WROW;
    const int lane = threadIdx.x & 31;
    const int w    = threadIdx.x >> 5;
    const int wc   = w % WCOL;
    const int wr   = w / WCOL;
    unsigned long long acc[ROWS];
#pragma unroll
    for (int i = 0; i < ROWS; i++) acc[i] = 0ull;

    const float* a0 = As + (size_t)(wr * ROWS) * lda;
    const float* Wp = W + 2 * lane + 64 * wc;

#pragma unroll 2
    for (int k0 = 0; k0 < KDIM; k0 += 4) {
        unsigned long long wv0 = *reinterpret_cast<const unsigned long long*>(Wp + (size_t)(k0 + 0) * NCOLS);
        unsigned long long wv1 = *reinterpret_cast<const unsigned long long*>(Wp + (size_t)(k0 + 1) * NCOLS);
        unsigned long long wv2 = *reinterpret_cast<const unsigned long long*>(Wp + (size_t)(k0 + 2) * NCOLS);
        unsigned long long wv3 = *reinterpret_cast<const unsigned long long*>(Wp + (size_t)(k0 + 3) * NCOLS);
#pragma unroll
        for (int i = 0; i < ROWS; i++) {
            float4 av = *reinterpret_cast<const float4*>(a0 + (size_t)i * lda + k0);
            ffma2(acc[i], pk2(av.x, av.x), wv0);
            ffma2(acc[i], pk2(av.y, av.y), wv1);
            ffma2(acc[i], pk2(av.z, av.z), wv2);
            ffma2(acc[i], pk2(av.w, av.w), wv3);
        }
    }
#pragma unroll
    for (int i = 0; i < ROWS; i++) {
        int row = wr * ROWS + i;
        float x, y; upk2(acc[i], x, y);
        int col = 2 * lane + 64 * wc;
        epi(row, col, x, y);
        Cs[(size_t)row * ldc + col]     = x;
        Cs[(size_t)row * ldc + col + 1] = y;
    }
}

__global__ void STG_zero_kernel() {
    size_t i = ((size_t)blockIdx.x * 256 + threadIdx.x) * 4;
    const size_t nH = (size_t)NE_ * H_;
    if (i < nH) {
        *reinterpret_cast<float4*>(g_h + i) = make_float4(0.f, 0.f, 0.f, 0.f);
    } else {
        size_t j = i - nH;
        if (j < (size_t)NE_ * 8)
            *reinterpret_cast<float4*>(g_den + j) = make_float4(0.f, 0.f, 0.f, 0.f);
    }
}

__global__ __launch_bounds__(256) void STG_qall_kernel(
    const float* __restrict__ ent, const float* __restrict__ Wq, const float* __restrict__ bq)
{
    extern __shared__ float sm[];
    float* h_s = sm;
    float* o_s = sm + 64 * 128;
    const int row0 = blockIdx.x * 64;
    for (int t = threadIdx.x; t < 64 * 32; t += 256) {
        int r = t >> 5, c = (t & 31) * 4; int g = row0 + r;
        float4 v = make_float4(0.f, 0.f, 0.f, 0.f);
        if (g < NE_) v = *reinterpret_cast<const float4*>(ent + (size_t)g * H_ + c);
        *reinterpret_cast<float4*>(h_s + r * H_ + c) = v;
    }
    __syncthreads();
    gemmC<64, 128, 128>(h_s, 128, Wq, o_s, 128,
        [&](int r, int c, float& x, float& y) { x += bq[c]; y += bq[c + 1]; });
    __syncthreads();
    for (int t = threadIdx.x; t < 64 * 32; t += 256) {
        int r = t >> 5, c = (t & 31) * 4; int g = row0 + r;
        if (g < NE_)
            *reinterpret_cast<float4*>(g_q + (size_t)g * H_ + c) =
                *reinterpret_cast<const float4*>(o_s + r * H_ + c);
    }
}

__global__ __launch_bounds__(256, 2) void STG_edge_kernel(
    const float* __restrict__ ent, const float* __restrict__ drel,
    const float* __restrict__ Wk, const float* __restrict__ bk,
    const float* __restrict__ Wv, const float* __restrict__ bv,
    const float* __restrict__ wgW1, const float* __restrict__ wgb1,
    const float* __restrict__ wgW2, const float* __restrict__ wgb2,
    const float* __restrict__ time_coeff,
    const float* __restrict__ edge_time, const float* __restrict__ query_time,
    const int* __restrict__ src, const int* __restrict__ dst, const int* __restrict__ etyp)
{
    extern __shared__ float sm[];
    float* wi_s  = sm;
    float* hid_s = wi_s + 32 * 256;
    float* k_s   = hid_s + 32 * 128;
    float* v_s   = k_s + 32 * 128;
    float* tm_s  = v_s + 32 * 128;
    float* dw_s  = tm_s + 32;
    float* ex_s  = dw_s + 32;
    int*   dst_s = (int*)(ex_s + 32 * 8);
    int*   src_s = dst_s + 32;
    int*   et_s  = src_s + 32;
    int*   vld_s = et_s + 32;

    const int tid = threadIdx.x;
    if (tid < 32) {
        int e = blockIdx.x * 32 + tid;
        int vld = (e < E_);
        int ee = vld ? e : 0;
        int s = src[ee], d = dst[ee], t = etyp[ee];
        float tc = fabsf(time_coeff[0]) + 1e-9f;
        float dte = (query_time[d] - edge_time[ee]) / tc;
        tm_s[tid] = sigmoid_f(dte);
        dst_s[tid] = d; src_s[tid] = s; et_s[tid] = t; vld_s[tid] = vld;
    }
    __syncthreads();

    for (int t = tid; t < 32 * 64; t += 256) {
        int r = t >> 6; int c = (t & 63) * 4;
        float4 v;
        if (c < 128) {
            v = *reinterpret_cast<const float4*>(ent + (size_t)src_s[r] * H_ + c);
        } else {
            float4 rv = *reinterpret_cast<const float4*>(drel + (size_t)et_s[r] * H_ + (c - 128));
            float tmv = tm_s[r];
            v.x = rv.x * tmv; v.y = rv.y * tmv; v.z = rv.z * tmv; v.w = rv.w * tmv;
        }
        *reinterpret_cast<float4*>(wi_s + r * 256 + c) = v;
    }
    __syncthreads();

    gemmC<32, 128, 256>(wi_s, 256, wgW1, hid_s, 128,
        [&](int r, int c, float& x, float& y) {
            float tmv = tm_s[r];
            x = fmaxf(x + wgb1[c]     + tmv * wgW1[256 * 128 + c],     0.f);
            y = fmaxf(y + wgb1[c + 1] + tmv * wgW1[256 * 128 + c + 1], 0.f);
        });
    __syncthreads();

    {
        int r = tid >> 3, part = tid & 7;
        float s = 0.f;
#pragma unroll
        for (int j = 0; j < 16; j++) { int d = part * 16 + j; s += hid_s[r * 128 + d] * wgW2[d]; }
        s += __shfl_xor_sync(0xffffffffu, s, 1);
        s += __shfl_xor_sync(0xffffffffu, s, 2);
        s += __shfl_xor_sync(0xffffffffu, s, 4);
        if (part == 0) dw_s[r] = sigmoid_f(s + wgb2[0]);
    }
    __syncthreads();

    for (int t = tid; t < 32 * 32; t += 256) {
        int r = t >> 5, c = (t & 31) * 4;
        float4 a = *reinterpret_cast<const float4*>(wi_s + r * 256 + c);
        float4 b = *reinterpret_cast<const float4*>(wi_s + r * 256 + 128 + c);
        float dw = dw_s[r];
        a.x *= b.x * dw; a.y *= b.y * dw; a.z *= b.z * dw; a.w *= b.w * dw;
        *reinterpret_cast<float4*>(wi_s + r * 256 + c) = a;
    }
    __syncthreads();

    gemmC<32, 128, 128>(wi_s, 256, Wk, k_s, 128,
        [&](int r, int c, float& x, float& y) { x += bk[c]; y += bk[c + 1]; });
    gemmC<32, 128, 128>(wi_s, 256, Wv, v_s, 128,
        [&](int r, int c, float& x, float& y) { x += bv[c]; y += bv[c + 1]; });
    __syncthreads();

    {
        int r = tid >> 3, hh = tid & 7;
        int d = dst_s[r]; int vld = vld_s[r];
        const float* qrow = g_q + (size_t)d * H_;
        float s = 0.f;
#pragma unroll
        for (int j = 0; j < 16; j += 4) {
            float4 qv = *reinterpret_cast<const float4*>(qrow + hh * 16 + j);
            float4 kv = *reinterpret_cast<const float4*>(k_s + r * 128 + hh * 16 + j);
            s += qv.x * kv.x + qv.y * kv.y + qv.z * kv.z + qv.w * kv.w;
        }
        float ex = expf(s * 0.25f);
        ex_s[r * 8 + hh] = ex;
        if (vld) atomicAdd(&g_den[(size_t)d * 8 + hh], ex);
    }
    __syncthreads();

    {
        int r = tid >> 3, part = tid & 7;
        if (vld_s[r]) {
            int d = dst_s[r];
            float* xr = g_h + (size_t)d * H_;
            float exh0 = ex_s[r * 8 + part];
#pragma unroll
            for (int j = 0; j < 16; j++) {
                int c = part * 16 + j;
                atomicAdd(&xr[c], exh0 * v_s[r * 128 + c]);
            }
        }
    }
}

__global__ void STG_norm_kernel() {
    size_t i = (size_t)blockIdx.x * 256 + threadIdx.x;
    if (i >= (size_t)NE_ * H_) return;
    size_t n = i >> 7; int c = (int)(i & 127);
    float den = g_den[n * 8 + (c >> 4)];
    float x = g_h[i];
    g_h[i] = den > 0.f ? x / den : 0.f;
}

__global__ void STG_relcopy_kernel(const float* __restrict__ rel) {
    int i = blockIdx.x * 256 + threadIdx.x;
    if (i < NR_ * H_) g_h[(size_t)NE_ * H_ + i] = rel[i];
}

// ---------------- tensor-core feval ----------------
#define SA_H 132
#define SA_A 260

__global__ __launch_bounds__(256) void STG_feval_kernel(
    int nk, float c1, float c2, float c3, float c4, float c5, int kout_idx,
    const float* __restrict__ spb1, const float* __restrict__ spb2,
    const float* __restrict__ tmb1, const float* __restrict__ tmb2,
    const float* __restrict__ fgW,  const float* __restrict__ fgb)
{
    extern __shared__ float sm[];
    float* h_s  = sm;                          // 128 x 132
    float* a1_s = sm + 128 * SA_H;             // 128 x 260
    uint4* Ws   = (uint4*)(a1_s + 128 * SA_A); // 1024 uint4 (16KB)

    const int tid  = threadIdx.x;
    const int lane = tid & 31;
    const int wid  = tid >> 5;       // warp = m-tile (16 rows)
    const int arow = wid * 16;
    const int g    = lane >> 2, q = lane & 3;
    const int row0 = blockIdx.x * 128;

    // prologue: h + sum c_j k_j  -> h_s (padded)
    for (int t = tid; t < 128 * 32; t += 256) {
        int r = t >> 5, c = (t & 31) * 4; int gr = row0 + r;
        float4 v = make_float4(0.f, 0.f, 0.f, 0.f);
        if (gr < NROWS_) {
            size_t idx = (size_t)gr * H_ + c;
            v = *reinterpret_cast<const float4*>(g_h + idx);
            float4 a;
            if (nk > 0) { a = *reinterpret_cast<const float4*>(g_k[0] + idx);
                v.x += c1 * a.x; v.y += c1 * a.y; v.z += c1 * a.z; v.w += c1 * a.w; }
            if (nk > 1) { a = *reinterpret_cast<const float4*>(g_k[1] + idx);
                v.x += c2 * a.x; v.y += c2 * a.y; v.z += c2 * a.z; v.w += c2 * a.w; }
            if (nk > 2) { a = *reinterpret_cast<const float4*>(g_k[2] + idx);
                v.x += c3 * a.x; v.y += c3 * a.y; v.z += c3 * a.z; v.w += c3 * a.w; }
            if (nk > 3) { a = *reinterpret_cast<const float4*>(g_k[3] + idx);
                v.x += c4 * a.x; v.y += c4 * a.y; v.z += c4 * a.z; v.w += c4 * a.w; }
            if (nk > 4) { a = *reinterpret_cast<const float4*>(g_k[4] + idx);
                v.x += c5 * a.x; v.y += c5 * a.y; v.z += c5 * a.z; v.w += c5 * a.w; }
        }
        *reinterpret_cast<float4*>(h_s + (size_t)r * SA_H + c) = v;
    }
    // tm1: a2 = softplus(h @ tmW1 + tmb1)   (acc in regs, 8 n-tiles)
    float4 a2a[8];
#pragma unroll
    for (int i = 0; i < 8; i++) a2a[i] = make_float4(0.f, 0.f, 0.f, 0.f);
    mma_gemm<16, 8, 8, SA_H>(h_s, arow, g_f_tmW1, 0, Ws, a2a, tid, lane);
#pragma unroll
    for (int nt = 0; nt < 8; nt++) {
        int c0 = nt * 8 + 2 * q;
        float b0 = tmb1[c0], b1 = tmb1[c0 + 1];
        a2a[nt].x = softplus_f(a2a[nt].x + b0);
        a2a[nt].y = softplus_f(a2a[nt].y + b1);
        a2a[nt].z = softplus_f(a2a[nt].z + b0);
        a2a[nt].w = softplus_f(a2a[nt].w + b1);
    }
    // GEMM1 (2 passes of 128 cols): a1 = gelu(h @ spW1 + spb1) -> a1_s
#pragma unroll 1
    for (int pass = 0; pass < 2; pass++) {
        float4 g1[16];
#pragma unroll
        for (int i = 0; i < 16; i++) g1[i] = make_float4(0.f, 0.f, 0.f, 0.f);
        mma_gemm<16, 16, 32, SA_H>(h_s, arow, g_f_spW1, pass * 16, Ws, g1, tid, lane);
#pragma unroll
        for (int nt = 0; nt < 16; nt++) {
            int c0 = pass * 128 + nt * 8 + 2 * q;
            float b0 = spb1[c0], b1 = spb1[c0 + 1];
            float2 lo = make_float2(gelu_f(g1[nt].x + b0), gelu_f(g1[nt].y + b1));
            float2 hi = make_float2(gelu_f(g1[nt].z + b0), gelu_f(g1[nt].w + b1));
            *reinterpret_cast<float2*>(a1_s + (size_t)(arow + g) * SA_A + c0)     = lo;
            *reinterpret_cast<float2*>(a1_s + (size_t)(arow + g + 8) * SA_A + c0) = hi;
        }
    }
    // dump a2 regs -> h_s cols 0..63 (own rows; ordered by next barrier)
#pragma unroll
    for (int nt = 0; nt < 8; nt++) {
        int c0 = nt * 8 + 2 * q;
        *reinterpret_cast<float2*>(h_s + (size_t)(arow + g) * SA_H + c0)     = make_float2(a2a[nt].x, a2a[nt].y);
        *reinterpret_cast<float2*>(h_s + (size_t)(arow + g + 8) * SA_H + c0) = make_float2(a2a[nt].z, a2a[nt].w);
    }
    // GEMM2: sp = a1 @ spW2 + spb2   (acc regs, 16 n-tiles)
    float4 sp[16];
#pragma unroll
    for (int i = 0; i < 16; i++) sp[i] = make_float4(0.f, 0.f, 0.f, 0.f);
    mma_gemm<32, 16, 16, SA_A>(a1_s, arow, g_f_spW2, 0, Ws, sp, tid, lane);
    // tm2: tm = a2 @ tmW2 + tmb2  (a2 in h_s cols 0..63)
    float4 tm[16];
#pragma unroll
    for (int i = 0; i < 16; i++) tm[i] = make_float4(0.f, 0.f, 0.f, 0.f);
    mma_gemm<8, 16, 16, SA_H>(h_s, arow, g_f_tmW2, 0, Ws, tm, tid, lane);
#pragma unroll
    for (int nt = 0; nt < 16; nt++) {
        int c0 = nt * 8 + 2 * q;
        float sb0 = spb2[c0], sb1 = spb2[c0 + 1];
        float tb0 = tmb2[c0], tb1 = tmb2[c0 + 1];
        sp[nt].x += sb0; sp[nt].y += sb1; sp[nt].z += sb0; sp[nt].w += sb1;
        tm[nt].x += tb0; tm[nt].y += tb1; tm[nt].z += tb0; tm[nt].w += tb1;
    }
    // gate: per row r: g = sigmoid([sp,tm] @ fgW + fgb); out = g0*sp + g1*tm
    float s0a = 0.f, s1a = 0.f, s0b = 0.f, s1b = 0.f;
#pragma unroll
    for (int nt = 0; nt < 16; nt++) {
        int c0 = nt * 8 + 2 * q;
        float w00 = fgW[2 * c0],           w01 = fgW[2 * c0 + 1];
        float w10 = fgW[2 * (c0 + 1)],     w11 = fgW[2 * (c0 + 1) + 1];
        float u00 = fgW[2 * (128 + c0)],   u01 = fgW[2 * (128 + c0) + 1];
        float u10 = fgW[2 * (128 + c0+1)], u11 = fgW[2 * (128 + c0 + 1) + 1];
        s0a += sp[nt].x * w00 + sp[nt].y * w10 + tm[nt].x * u00 + tm[nt].y * u10;
        s1a += sp[nt].x * w01 + sp[nt].y * w11 + tm[nt].x * u01 + tm[nt].y * u11;
        s0b += sp[nt].z * w00 + sp[nt].w * w10 + tm[nt].z * u00 + tm[nt].w * u10;
        s1b += sp[nt].z * w01 + sp[nt].w * w11 + tm[nt].z * u01 + tm[nt].w * u11;
    }
    s0a += __shfl_xor_sync(0xffffffffu, s0a, 1); s0a += __shfl_xor_sync(0xffffffffu, s0a, 2);
    s1a += __shfl_xor_sync(0xffffffffu, s1a, 1); s1a += __shfl_xor_sync(0xffffffffu, s1a, 2);
    s0b += __shfl_xor_sync(0xffffffffu, s0b, 1); s0b += __shfl_xor_sync(0xffffffffu, s0b, 2);
    s1b += __shfl_xor_sync(0xffffffffu, s1b, 1); s1b += __shfl_xor_sync(0xffffffffu, s1b, 2);
    float g0a = sigmoid_f(s0a + fgb[0]), g1a = sigmoid_f(s1a + fgb[1]);
    float g0b = sigmoid_f(s0b + fgb[0]), g1b = sigmoid_f(s1b + fgb[1]);

    int ra = row0 + arow + g;
    int rb = ra + 8;
    float* ko = g_k[kout_idx];
#pragma unroll
    for (int nt = 0; nt < 16; nt++) {
        int c0 = nt * 8 + 2 * q;
        if (ra < NROWS_)
            *reinterpret_cast<float2*>(ko + (size_t)ra * H_ + c0) =
                make_float2(g0a * sp[nt].x + g1a * tm[nt].x, g0a * sp[nt].y + g1a * tm[nt].y);
        if (rb < NROWS_)
            *reinterpret_cast<float2*>(ko + (size_t)rb * H_ + c0) =
                make_float2(g0b * sp[nt].z + g1b * tm[nt].z, g0b * sp[nt].w + g1b * tm[nt].w);
    }
}

__global__ void STG_combine_kernel(float b1, float b3, float b4, float b5, float b6) {
    size_t i = ((size_t)blockIdx.x * 256 + threadIdx.x) * 4;
    if (i >= (size_t)NROWS_ * H_) return;
    float4 h = *reinterpret_cast<const float4*>(g_h + i);
    float4 a = *reinterpret_cast<const float4*>(g_k[0] + i);
    float4 c = *reinterpret_cast<const float4*>(g_k[2] + i);
    float4 d = *reinterpret_cast<const float4*>(g_k[3] + i);
    float4 e = *reinterpret_cast<const float4*>(g_k[4] + i);
    float4 f = *reinterpret_cast<const float4*>(g_k[5] + i);
    h.x += b1 * a.x + b3 * c.x + b4 * d.x + b5 * e.x + b6 * f.x;
    h.y += b1 * a.y + b3 * c.y + b4 * d.y + b5 * e.y + b6 * f.y;
    h.z += b1 * a.z + b3 * c.z + b4 * d.z + b5 * e.z + b6 * f.z;
    h.w += b1 * a.w + b3 * c.w + b4 * d.w + b5 * e.w + b6 * f.w;
    *reinterpret_cast<float4*>(g_h + i) = h;
}

__global__ void STG_outcopy_kernel(float* __restrict__ out, int n4) {
    int i = blockIdx.x * 256 + threadIdx.x;
    if (i < n4)
        *reinterpret_cast<float4*>(out + (size_t)i * 4) =
            *reinterpret_cast<const float4*>(g_h + (size_t)i * 4);
}

extern "C" void kernel_launch(void* const* d_in, const int* in_sizes, int n_in,
                              void* d_out, int out_size)
{
    (void)in_sizes; (void)n_in;
    const float* ent  = (const float*)d_in[0];
    const float* rel  = (const float*)d_in[1];
    const float* drel = (const float*)d_in[2];
    const float* Wq   = (const float*)d_in[3];
    const float* bq   = (const float*)d_in[4];
    const float* Wk   = (const float*)d_in[5];
    const float* bk   = (const float*)d_in[6];
    const float* Wv   = (const float*)d_in[7];
    const float* bv   = (const float*)d_in[8];
    const float* tcoef= (const float*)d_in[9];
    const float* wgW1 = (const float*)d_in[10];
    const float* wgb1 = (const float*)d_in[11];
    const float* wgW2 = (const float*)d_in[12];
    const float* wgb2 = (const float*)d_in[13];
    const float* spW1 = (const float*)d_in[14];
    const float* spb1 = (const float*)d_in[15];
    const float* spW2 = (const float*)d_in[16];
    const float* spb2 = (const float*)d_in[17];
    const float* tmW1 = (const float*)d_in[18];
    const float* tmb1 = (const float*)d_in[19];
    const float* tmW2 = (const float*)d_in[20];
    const float* tmb2 = (const float*)d_in[21];
    const float* fgW  = (const float*)d_in[22];
    const float* fgb  = (const float*)d_in[23];
    const float* edge_time  = (const float*)d_in[24];
    const float* query_time = (const float*)d_in[25];
    const int* src  = (const int*)d_in[26];
    const int* dst  = (const int*)d_in[27];
    const int* etyp = (const int*)d_in[28];
    float* out = (float*)d_out;

    const int SM_QALL = 2 * 64 * 128 * 4;
    const int SM_EDGE = (32*256 + 3*32*128 + 32 + 32 + 32*8 + 4*32) * 4;
    const int SM_FEVL = (128 * SA_H + 128 * SA_A) * 4 + 1024 * 16;  // 217088
    cudaFuncSetAttribute(STG_qall_kernel,  cudaFuncAttributeMaxDynamicSharedMemorySize, SM_QALL);
    cudaFuncSetAttribute(STG_edge_kernel,  cudaFuncAttributeMaxDynamicSharedMemorySize, SM_EDGE);
    cudaFuncSetAttribute(STG_feval_kernel, cudaFuncAttributeMaxDynamicSharedMemorySize, SM_FEVL);

    STG_fragrepack_kernel<<<160, 256>>>(spW1, spW2, tmW1, tmW2);

    {
        size_t tot4 = ((size_t)NE_ * H_ + (size_t)NE_ * 8) / 4;
        int nb = (int)((tot4 + 255) / 256);
        STG_zero_kernel<<<nb, 256>>>();
    }
    STG_qall_kernel<<<(NE_ + 63) / 64, 256, SM_QALL>>>(ent, Wq, bq);
    STG_edge_kernel<<<(E_ + 31) / 32, 256, SM_EDGE>>>(
        ent, drel, Wk, bk, Wv, bv, wgW1, wgb1, wgW2, wgb2,
        tcoef, edge_time, query_time, src, dst, etyp);
    {
        size_t tot = (size_t)NE_ * H_;
        STG_norm_kernel<<<(int)((tot + 255) / 256), 256>>>();
    }
    STG_relcopy_kernel<<<(NR_ * H_ + 255) / 256, 256>>>(rel);

    const float dt = 1.0f / 8.0f;
    const int FB = (NROWS_ + 127) / 128;
    const int CB = (int)(((size_t)NROWS_ * H_ / 4 + 255) / 256);

    for (int s = 0; s < 8; s++) {
        STG_feval_kernel<<<FB, 256, SM_FEVL>>>(0, 0.f, 0.f, 0.f, 0.f, 0.f, 0,
            spb1, spb2, tmb1, tmb2, fgW, fgb);
        STG_feval_kernel<<<FB, 256, SM_FEVL>>>(1, dt * 0.2f, 0.f, 0.f, 0.f, 0.f, 1,
            spb1, spb2, tmb1, tmb2, fgW, fgb);
        STG_feval_kernel<<<FB, 256, SM_FEVL>>>(2,
            dt * (3.0f / 40.0f), dt * (9.0f / 40.0f), 0.f, 0.f, 0.f, 2,
            spb1, spb2, tmb1, tmb2, fgW, fgb);
        STG_feval_kernel<<<FB, 256, SM_FEVL>>>(3,
            dt * (44.0f / 45.0f), dt * (-56.0f / 15.0f), dt * (32.0f / 9.0f), 0.f, 0.f, 3,
            spb1, spb2, tmb1, tmb2, fgW, fgb);
        STG_feval_kernel<<<FB, 256, SM_FEVL>>>(4,
            dt * (19372.0f / 6561.0f), dt * (-25360.0f / 2187.0f),
            dt * (64448.0f / 6561.0f), dt * (-212.0f / 729.0f), 0.f, 4,
            spb1, spb2, tmb1, tmb2, fgW, fgb);
        STG_feval_kernel<<<FB, 256, SM_FEVL>>>(5,
            dt * (9017.0f / 3168.0f), dt * (-355.0f / 33.0f),
            dt * (46732.0f / 5247.0f), dt * (49.0f / 176.0f),
            dt * (-5103.0f / 18656.0f), 5,
            spb1, spb2, tmb1, tmb2, fgW, fgb);
        STG_combine_kernel<<<CB, 256>>>(
            dt * (35.0f / 384.0f), dt * (500.0f / 1113.0f), dt * (125.0f / 192.0f),
            dt * (-2187.0f / 6784.0f), dt * (11.0f / 84.0f));
    }

    {
        int n4 = out_size / 4;
        STG_outcopy_kernel<<<(n4 + 255) / 256, 256>>>(out, n4);
    }
}